// round 2
// baseline (speedup 1.0000x reference)
#include <cuda_runtime.h>
#include <cuda_bf16.h>
#include <cstdint>

// ---------------------------------------------------------------------------
// FactorizedLayer on GB300 (sm_103a) — base-PTX-target build (no tcgen05!)
//   out[b,h] = 0.5*sum_l[(x.beta_hl)^2 - (x^2 . beta_hl^2)] + x.W_h + b_h
// ssq collapses via G_h[n] = sum_l beta[h,l,n]^2.
// Two bf16 mma.sync GEMMs, fp32 recovered via bf16 hi/lo K-stacking:
//   main: S = [Xhi|Xhi|Xlo](4096x1536) @ [Bhi|Blo|Bhi]^T (8192 rows)
//         epilogue: out[b,h] += 0.5 * sum over groups of 8 cols of S^2
//   aux : out = [Xhi|X2hi|X2hi|X2lo](4096x2048) @ [Whi|Ghi|Glo|Ghi]^T (1024) + b
//         (G pre-scaled by -0.5)
// ---------------------------------------------------------------------------

#define DB 4096
#define DN 512
#define DH 1024
#define DL 8
#define RM (DH*DL)

__device__ __align__(16) __nv_bfloat16 g_Am[(size_t)DB * 1536];
__device__ __align__(16) __nv_bfloat16 g_Bm[(size_t)RM * 1536];
__device__ __align__(16) __nv_bfloat16 g_Aa[(size_t)DB * 2048];
__device__ __align__(16) __nv_bfloat16 g_Ba[(size_t)DH * 2048];

// ------------------------------- prep kernels ------------------------------

__global__ void prep_A(const float* __restrict__ x) {
    int i = blockIdx.x * 256 + threadIdx.x;          // over 4096*512
    int m = i >> 9, n = i & 511;
    float v = x[i];
    __nv_bfloat16 h = __float2bfloat16(v);
    __nv_bfloat16 l = __float2bfloat16(v - __bfloat162float(h));
    size_t bm = (size_t)m * 1536;
    g_Am[bm + n] = h; g_Am[bm + 512 + n] = h; g_Am[bm + 1024 + n] = l;
    float v2 = v * v;
    __nv_bfloat16 h2 = __float2bfloat16(v2);
    __nv_bfloat16 l2 = __float2bfloat16(v2 - __bfloat162float(h2));
    size_t ba = (size_t)m * 2048;
    g_Aa[ba + n] = h; g_Aa[ba + 512 + n] = h2;
    g_Aa[ba + 1024 + n] = h2; g_Aa[ba + 1536 + n] = l2;
}

__global__ void prep_Bm(const float* __restrict__ beta) {
    int i = blockIdx.x * 256 + threadIdx.x;          // over 8192*512
    int r = i >> 9, n = i & 511;
    float v = beta[i];
    __nv_bfloat16 h = __float2bfloat16(v);
    __nv_bfloat16 l = __float2bfloat16(v - __bfloat162float(h));
    size_t b = (size_t)r * 1536;
    g_Bm[b + n] = h; g_Bm[b + 512 + n] = l; g_Bm[b + 1024 + n] = h;
}

__global__ void prep_Ba(const float* __restrict__ beta, const float* __restrict__ W) {
    int i = blockIdx.x * 256 + threadIdx.x;          // over 1024*512
    int hh = i >> 9, n = i & 511;
    float w = W[i];
    const float* bp = beta + (size_t)hh * (DL * DN) + n;
    float g = 0.f;
#pragma unroll
    for (int l = 0; l < DL; l++) { float t = bp[l * DN]; g += t * t; }
    g *= -0.5f;
    __nv_bfloat16 wh = __float2bfloat16(w);
    __nv_bfloat16 gh = __float2bfloat16(g);
    __nv_bfloat16 gl = __float2bfloat16(g - __bfloat162float(gh));
    size_t b = (size_t)hh * 2048;
    g_Ba[b + n] = wh; g_Ba[b + 512 + n] = gh;
    g_Ba[b + 1024 + n] = gl; g_Ba[b + 1536 + n] = gh;
}

// ------------------------------- GEMM ------------------------------------

__device__ __forceinline__ uint32_t swz(uint32_t o) { return o ^ ((o >> 3) & 0x70); }

constexpr int STAGES = 3;
constexpr int TILEB = 16384;                 // bytes per operand per stage (128 rows x 128B)
constexpr int SMEMB = STAGES * TILEB * 2;    // 98304

#define LDSM_X4(r, a)                                                           \
    asm volatile("ldmatrix.sync.aligned.m8n8.x4.shared.b16 {%0,%1,%2,%3}, [%4];"\
        : "=r"((r)[0]), "=r"((r)[1]), "=r"((r)[2]), "=r"((r)[3]) : "r"(a))

#define MMA16816(c, a, b0, b1)                                                  \
    asm volatile("mma.sync.aligned.m16n8k16.row.col.f32.bf16.bf16.f32 "         \
        "{%0,%1,%2,%3}, {%4,%5,%6,%7}, {%8,%9}, {%0,%1,%2,%3};"                 \
        : "+f"((c)[0]), "+f"((c)[1]), "+f"((c)[2]), "+f"((c)[3])                 \
        : "r"((a)[0]), "r"((a)[1]), "r"((a)[2]), "r"((a)[3]), "r"(b0), "r"(b1))

// MODE 0: aux (out = acc + bias[col]); MODE 1: main (out += 0.5*sum8(acc^2))
template <int MODE>
__global__ void __launch_bounds__(256, 1)
fm_gemm(const __nv_bfloat16* __restrict__ gA, const __nv_bfloat16* __restrict__ gB,
        float* __restrict__ out, const float* __restrict__ bias, int Kld, int KT)
{
    extern __shared__ __align__(128) char smem[];
    const uint32_t sb = (uint32_t)__cvta_generic_to_shared(smem);
    const int tid = threadIdx.x, lane = tid & 31, wid = tid >> 5;
    const int cm = blockIdx.y * 128, cn = blockIdx.x * 128;
    const int wm = (wid & 1) * 64, wn = (wid >> 1) * 32;

    // cp.async lane mapping: 32 rows x 8 chunks of 16B per pass, 4 passes
    const int lrow = tid >> 3;
    const int lchunk = tid & 7;
    const __nv_bfloat16* gArow = gA + (size_t)(cm + lrow) * Kld + lchunk * 8;
    const __nv_bfloat16* gBrow = gB + (size_t)(cn + lrow) * Kld + lchunk * 8;

    // ldmatrix lane mapping
    const int a_row = wm + (lane & 15);
    const int a_ko  = ((lane >> 4) & 1) * 16;
    const int b_mi  = lane >> 3;
    const int b_row = wn + ((b_mi >> 1) & 1) * 8 + (lane & 7);
    const int b_ko  = (b_mi & 1) * 16;

    float acc[4][4][4];
#pragma unroll
    for (int i = 0; i < 4; i++)
#pragma unroll
        for (int j = 0; j < 4; j++)
#pragma unroll
            for (int q = 0; q < 4; q++) acc[i][j][q] = 0.f;

    auto load_stage = [&](int s, int kt) {
        const uint32_t sa = sb + s * TILEB;
        const uint32_t sB = sb + STAGES * TILEB + s * TILEB;
        const int koff = kt * 64;
#pragma unroll
        for (int i = 0; i < 4; i++) {
            uint32_t da = sa + swz((lrow + i * 32) * 128 + lchunk * 16);
            const void* ga = gArow + (size_t)(i * 32) * Kld + koff;
            asm volatile("cp.async.cg.shared.global [%0], [%1], 16;" :: "r"(da), "l"(ga));
            uint32_t db = sB + swz((lrow + i * 32) * 128 + lchunk * 16);
            const void* gb = gBrow + (size_t)(i * 32) * Kld + koff;
            asm volatile("cp.async.cg.shared.global [%0], [%1], 16;" :: "r"(db), "l"(gb));
        }
    };

    auto compute = [&](int s) {
        const uint32_t sa = sb + s * TILEB;
        const uint32_t sB = sb + STAGES * TILEB + s * TILEB;
#pragma unroll
        for (int ks = 0; ks < 4; ks++) {
            uint32_t a[4][4];
#pragma unroll
            for (int mt = 0; mt < 4; mt++) {
                uint32_t addr = sa + swz((a_row + mt * 16) * 128 + ks * 32 + a_ko);
                LDSM_X4(a[mt], addr);
            }
            uint32_t b[2][4];
#pragma unroll
            for (int jj = 0; jj < 2; jj++) {
                uint32_t addr = sB + swz((b_row + jj * 16) * 128 + ks * 32 + b_ko);
                LDSM_X4(b[jj], addr);
            }
#pragma unroll
            for (int mt = 0; mt < 4; mt++)
#pragma unroll
                for (int nt = 0; nt < 4; nt++)
                    MMA16816(acc[mt][nt], a[mt], b[nt >> 1][(nt & 1) * 2], b[nt >> 1][(nt & 1) * 2 + 1]);
        }
    };

    load_stage(0, 0);
    asm volatile("cp.async.commit_group;" ::: "memory");
    load_stage(1, 1);
    asm volatile("cp.async.commit_group;" ::: "memory");

    for (int kt = 0; kt < KT; kt++) {
        asm volatile("cp.async.wait_group 1;" ::: "memory");
        __syncthreads();
        if (kt + 2 < KT) load_stage((kt + 2) % STAGES, kt + 2);
        asm volatile("cp.async.commit_group;" ::: "memory");
        compute(kt % STAGES);
    }

    // ------------------------------ epilogue ------------------------------
#pragma unroll
    for (int mt = 0; mt < 4; mt++) {
        const int row  = cm + wm + mt * 16 + (lane >> 2);
        const int row2 = row + 8;
#pragma unroll
        for (int nt = 0; nt < 4; nt++) {
            if (MODE == 0) {
                const int col = cn + wn + nt * 8 + (lane & 3) * 2;
                float2 bb = *(const float2*)(bias + col);
                float2 v0 = { acc[mt][nt][0] + bb.x, acc[mt][nt][1] + bb.y };
                float2 v1 = { acc[mt][nt][2] + bb.x, acc[mt][nt][3] + bb.y };
                *(float2*)(out + (size_t)row  * DH + col) = v0;
                *(float2*)(out + (size_t)row2 * DH + col) = v1;
            } else {
                float s0 = acc[mt][nt][0] * acc[mt][nt][0] + acc[mt][nt][1] * acc[mt][nt][1];
                float s1 = acc[mt][nt][2] * acc[mt][nt][2] + acc[mt][nt][3] * acc[mt][nt][3];
                s0 += __shfl_xor_sync(0xffffffffu, s0, 1);
                s0 += __shfl_xor_sync(0xffffffffu, s0, 2);
                s1 += __shfl_xor_sync(0xffffffffu, s1, 1);
                s1 += __shfl_xor_sync(0xffffffffu, s1, 2);
                if ((lane & 3) == 0) {
                    const int h = (cn + wn) / 8 + nt;
                    out[(size_t)row  * DH + h] += 0.5f * s0;
                    out[(size_t)row2 * DH + h] += 0.5f * s1;
                }
            }
        }
    }
}

// --------------------------------- host side --------------------------------

extern "C" void kernel_launch(void* const* d_in, const int* in_sizes, int n_in,
                              void* d_out, int out_size) {
    const float* x    = (const float*)d_in[0];
    const float* beta = (const float*)d_in[1];
    const float* W    = (const float*)d_in[2];
    const float* bias = (const float*)d_in[3];
    float* out = (float*)d_out;
    (void)in_sizes; (void)n_in; (void)out_size;

    void *pAm, *pBm, *pAa, *pBa;
    cudaGetSymbolAddress(&pAm, g_Am);
    cudaGetSymbolAddress(&pBm, g_Bm);
    cudaGetSymbolAddress(&pAa, g_Aa);
    cudaGetSymbolAddress(&pBa, g_Ba);

    cudaFuncSetAttribute((const void*)fm_gemm<0>,
                         cudaFuncAttributeMaxDynamicSharedMemorySize, SMEMB);
    cudaFuncSetAttribute((const void*)fm_gemm<1>,
                         cudaFuncAttributeMaxDynamicSharedMemorySize, SMEMB);

    prep_A <<<(DB * DN) / 256, 256>>>(x);
    prep_Bm<<<(RM * DN) / 256, 256>>>(beta);
    prep_Ba<<<(DH * DN) / 256, 256>>>(beta, W);

    // aux first: writes every out element (= linear + bias - 0.5*ssq)
    fm_gemm<0><<<dim3(DH / 128, DB / 128), 256, SMEMB>>>(
        (const __nv_bfloat16*)pAa, (const __nv_bfloat16*)pBa, out, bias, 2048, 32);
    // main: read-modify-write adds 0.5 * sum_l s^2
    fm_gemm<1><<<dim3(RM / 128, DB / 128), 256, SMEMB>>>(
        (const __nv_bfloat16*)pAm, (const __nv_bfloat16*)pBm, out, bias, 1536, 24);
}

// round 3
// speedup vs baseline: 1.0200x; 1.0200x over previous
#include <cuda_runtime.h>
#include <cuda_bf16.h>
#include <cstdint>

// ---------------------------------------------------------------------------
// FactorizedLayer on GB300 (sm_103a) — base-PTX-target build (mma.sync path)
//   out[b,h] = 0.5*sum_l[(x.beta_hl)^2 - (x^2 . beta_hl^2)] + x.W_h + b_h
// ssq collapses via G_h[n] = sum_l beta[h,l,n]^2.
// Two bf16 mma.sync GEMMs, fp32 recovered via bf16 hi/lo K-stacking:
//   main: S = [Xhi|Xhi|Xlo](4096x1536) @ [Bhi|Blo|Bhi]^T (8192 rows)
//         epilogue: out[b,h] += 0.5 * sum over groups of 8 cols of S^2
//   aux : out = [Xhi|X2hi|X2hi|X2lo](4096x2048) @ [Whi|Ghi|Glo|Ghi]^T (1024) + b
//         (G pre-scaled by -0.5)
// R3: warp tile 64x32 -> 64x64 (CTA 128x256): HMMA:LDSM ratio 2.67 -> 4.0,
//     half the sync frequency per MMA. Pure tensor-pipe-efficiency change.
// ---------------------------------------------------------------------------

#define DB 4096
#define DN 512
#define DH 1024
#define DL 8
#define RM (DH*DL)

__device__ __align__(16) __nv_bfloat16 g_Am[(size_t)DB * 1536];
__device__ __align__(16) __nv_bfloat16 g_Bm[(size_t)RM * 1536];
__device__ __align__(16) __nv_bfloat16 g_Aa[(size_t)DB * 2048];
__device__ __align__(16) __nv_bfloat16 g_Ba[(size_t)DH * 2048];

// ------------------------------- prep kernels ------------------------------

__global__ void prep_A(const float* __restrict__ x) {
    int i = blockIdx.x * 256 + threadIdx.x;          // over 4096*512
    int m = i >> 9, n = i & 511;
    float v = x[i];
    __nv_bfloat16 h = __float2bfloat16(v);
    __nv_bfloat16 l = __float2bfloat16(v - __bfloat162float(h));
    size_t bm = (size_t)m * 1536;
    g_Am[bm + n] = h; g_Am[bm + 512 + n] = h; g_Am[bm + 1024 + n] = l;
    float v2 = v * v;
    __nv_bfloat16 h2 = __float2bfloat16(v2);
    __nv_bfloat16 l2 = __float2bfloat16(v2 - __bfloat162float(h2));
    size_t ba = (size_t)m * 2048;
    g_Aa[ba + n] = h; g_Aa[ba + 512 + n] = h2;
    g_Aa[ba + 1024 + n] = h2; g_Aa[ba + 1536 + n] = l2;
}

__global__ void prep_Bm(const float* __restrict__ beta) {
    int i = blockIdx.x * 256 + threadIdx.x;          // over 8192*512
    int r = i >> 9, n = i & 511;
    float v = beta[i];
    __nv_bfloat16 h = __float2bfloat16(v);
    __nv_bfloat16 l = __float2bfloat16(v - __bfloat162float(h));
    size_t b = (size_t)r * 1536;
    g_Bm[b + n] = h; g_Bm[b + 512 + n] = l; g_Bm[b + 1024 + n] = h;
}

__global__ void prep_Ba(const float* __restrict__ beta, const float* __restrict__ W) {
    int i = blockIdx.x * 256 + threadIdx.x;          // over 1024*512
    int hh = i >> 9, n = i & 511;
    float w = W[i];
    const float* bp = beta + (size_t)hh * (DL * DN) + n;
    float g = 0.f;
#pragma unroll
    for (int l = 0; l < DL; l++) { float t = bp[l * DN]; g += t * t; }
    g *= -0.5f;
    __nv_bfloat16 wh = __float2bfloat16(w);
    __nv_bfloat16 gh = __float2bfloat16(g);
    __nv_bfloat16 gl = __float2bfloat16(g - __bfloat162float(gh));
    size_t b = (size_t)hh * 2048;
    g_Ba[b + n] = wh; g_Ba[b + 512 + n] = gh;
    g_Ba[b + 1024 + n] = gl; g_Ba[b + 1536 + n] = gh;
}

// ------------------------------- GEMM ------------------------------------

__device__ __forceinline__ uint32_t swz(uint32_t o) { return o ^ ((o >> 3) & 0x70); }

constexpr int STAGES = 3;
constexpr int ABYTES = 128 * 128;             // 16384 (128 rows x 64k x 2B)
constexpr int BBYTES = 256 * 128;             // 32768 (256 rows x 64k x 2B)
constexpr int SMEMB = STAGES * (ABYTES + BBYTES);   // 147456

#define LDSM_X4(r, a)                                                           \
    asm volatile("ldmatrix.sync.aligned.m8n8.x4.shared.b16 {%0,%1,%2,%3}, [%4];"\
        : "=r"((r)[0]), "=r"((r)[1]), "=r"((r)[2]), "=r"((r)[3]) : "r"(a))

#define MMA16816(c, a, b0, b1)                                                  \
    asm volatile("mma.sync.aligned.m16n8k16.row.col.f32.bf16.bf16.f32 "         \
        "{%0,%1,%2,%3}, {%4,%5,%6,%7}, {%8,%9}, {%0,%1,%2,%3};"                 \
        : "+f"((c)[0]), "+f"((c)[1]), "+f"((c)[2]), "+f"((c)[3])                 \
        : "r"((a)[0]), "r"((a)[1]), "r"((a)[2]), "r"((a)[3]), "r"(b0), "r"(b1))

// MODE 0: aux (out = acc + bias[col]); MODE 1: main (out += 0.5*sum8(acc^2))
template <int MODE>
__global__ void __launch_bounds__(256, 1)
fm_gemm(const __nv_bfloat16* __restrict__ gA, const __nv_bfloat16* __restrict__ gB,
        float* __restrict__ out, const float* __restrict__ bias, int Kld, int KT)
{
    extern __shared__ __align__(128) char smem[];
    const uint32_t sb = (uint32_t)__cvta_generic_to_shared(smem);
    const int tid = threadIdx.x, lane = tid & 31, wid = tid >> 5;
    const int cm = blockIdx.y * 128, cn = blockIdx.x * 256;
    const int wm = (wid & 1) * 64, wn = (wid >> 1) * 64;   // 2x4 warps, 64x64 tiles

    // cp.async lane mapping: 32 rows x 8 chunks of 16B per pass
    const int lrow = tid >> 3;
    const int lchunk = tid & 7;
    const __nv_bfloat16* gArow = gA + (size_t)(cm + lrow) * Kld + lchunk * 8;
    const __nv_bfloat16* gBrow = gB + (size_t)(cn + lrow) * Kld + lchunk * 8;

    // ldmatrix lane mapping
    const int a_row = wm + (lane & 15);
    const int a_ko  = ((lane >> 4) & 1) * 16;
    const int b_mi  = lane >> 3;
    const int b_row = wn + ((b_mi >> 1) & 1) * 8 + (lane & 7);
    const int b_ko  = (b_mi & 1) * 16;

    float acc[4][8][4];
#pragma unroll
    for (int i = 0; i < 4; i++)
#pragma unroll
        for (int j = 0; j < 8; j++)
#pragma unroll
            for (int q = 0; q < 4; q++) acc[i][j][q] = 0.f;

    auto load_stage = [&](int s, int kt) {
        const uint32_t sa = sb + s * ABYTES;
        const uint32_t sB = sb + STAGES * ABYTES + s * BBYTES;
        const int koff = kt * 64;
#pragma unroll
        for (int i = 0; i < 4; i++) {
            uint32_t da = sa + swz((lrow + i * 32) * 128 + lchunk * 16);
            const void* ga = gArow + (size_t)(i * 32) * Kld + koff;
            asm volatile("cp.async.cg.shared.global [%0], [%1], 16;" :: "r"(da), "l"(ga));
        }
#pragma unroll
        for (int i = 0; i < 8; i++) {
            uint32_t db = sB + swz((lrow + i * 32) * 128 + lchunk * 16);
            const void* gb = gBrow + (size_t)(i * 32) * Kld + koff;
            asm volatile("cp.async.cg.shared.global [%0], [%1], 16;" :: "r"(db), "l"(gb));
        }
    };

    auto compute = [&](int s) {
        const uint32_t sa = sb + s * ABYTES;
        const uint32_t sB = sb + STAGES * ABYTES + s * BBYTES;
#pragma unroll
        for (int ks = 0; ks < 4; ks++) {
            uint32_t a[4][4];
#pragma unroll
            for (int mt = 0; mt < 4; mt++) {
                uint32_t addr = sa + swz((a_row + mt * 16) * 128 + ks * 32 + a_ko);
                LDSM_X4(a[mt], addr);
            }
            uint32_t b[4][4];
#pragma unroll
            for (int jj = 0; jj < 4; jj++) {
                uint32_t addr = sB + swz((b_row + jj * 16) * 128 + ks * 32 + b_ko);
                LDSM_X4(b[jj], addr);
            }
#pragma unroll
            for (int mt = 0; mt < 4; mt++)
#pragma unroll
                for (int nt = 0; nt < 8; nt++)
                    MMA16816(acc[mt][nt], a[mt], b[nt >> 1][(nt & 1) * 2], b[nt >> 1][(nt & 1) * 2 + 1]);
        }
    };

    load_stage(0, 0);
    asm volatile("cp.async.commit_group;" ::: "memory");
    load_stage(1, 1);
    asm volatile("cp.async.commit_group;" ::: "memory");

    for (int kt = 0; kt < KT; kt++) {
        asm volatile("cp.async.wait_group 1;" ::: "memory");
        __syncthreads();
        if (kt + 2 < KT) load_stage((kt + 2) % STAGES, kt + 2);
        asm volatile("cp.async.commit_group;" ::: "memory");
        compute(kt % STAGES);
    }

    // ------------------------------ epilogue ------------------------------
#pragma unroll
    for (int mt = 0; mt < 4; mt++) {
        const int row  = cm + wm + mt * 16 + (lane >> 2);
        const int row2 = row + 8;
#pragma unroll
        for (int nt = 0; nt < 8; nt++) {
            if (MODE == 0) {
                const int col = cn + wn + nt * 8 + (lane & 3) * 2;
                float2 bb = *(const float2*)(bias + col);
                float2 v0 = { acc[mt][nt][0] + bb.x, acc[mt][nt][1] + bb.y };
                float2 v1 = { acc[mt][nt][2] + bb.x, acc[mt][nt][3] + bb.y };
                *(float2*)(out + (size_t)row  * DH + col) = v0;
                *(float2*)(out + (size_t)row2 * DH + col) = v1;
            } else {
                float s0 = acc[mt][nt][0] * acc[mt][nt][0] + acc[mt][nt][1] * acc[mt][nt][1];
                float s1 = acc[mt][nt][2] * acc[mt][nt][2] + acc[mt][nt][3] * acc[mt][nt][3];
                s0 += __shfl_xor_sync(0xffffffffu, s0, 1);
                s0 += __shfl_xor_sync(0xffffffffu, s0, 2);
                s1 += __shfl_xor_sync(0xffffffffu, s1, 1);
                s1 += __shfl_xor_sync(0xffffffffu, s1, 2);
                if ((lane & 3) == 0) {
                    const int h = (cn + wn) / 8 + nt;
                    out[(size_t)row  * DH + h] += 0.5f * s0;
                    out[(size_t)row2 * DH + h] += 0.5f * s1;
                }
            }
        }
    }
}

// --------------------------------- host side --------------------------------

extern "C" void kernel_launch(void* const* d_in, const int* in_sizes, int n_in,
                              void* d_out, int out_size) {
    const float* x    = (const float*)d_in[0];
    const float* beta = (const float*)d_in[1];
    const float* W    = (const float*)d_in[2];
    const float* bias = (const float*)d_in[3];
    float* out = (float*)d_out;
    (void)in_sizes; (void)n_in; (void)out_size;

    void *pAm, *pBm, *pAa, *pBa;
    cudaGetSymbolAddress(&pAm, g_Am);
    cudaGetSymbolAddress(&pBm, g_Bm);
    cudaGetSymbolAddress(&pAa, g_Aa);
    cudaGetSymbolAddress(&pBa, g_Ba);

    cudaFuncSetAttribute((const void*)fm_gemm<0>,
                         cudaFuncAttributeMaxDynamicSharedMemorySize, SMEMB);
    cudaFuncSetAttribute((const void*)fm_gemm<1>,
                         cudaFuncAttributeMaxDynamicSharedMemorySize, SMEMB);

    prep_A <<<(DB * DN) / 256, 256>>>(x);
    prep_Bm<<<(RM * DN) / 256, 256>>>(beta);
    prep_Ba<<<(DH * DN) / 256, 256>>>(beta, W);

    // aux first: writes every out element (= linear + bias - 0.5*ssq)
    fm_gemm<0><<<dim3(DH / 256, DB / 128), 256, SMEMB>>>(
        (const __nv_bfloat16*)pAa, (const __nv_bfloat16*)pBa, out, bias, 2048, 32);
    // main: read-modify-write adds 0.5 * sum_l s^2
    fm_gemm<1><<<dim3(RM / 256, DB / 128), 256, SMEMB>>>(
        (const __nv_bfloat16*)pAm, (const __nv_bfloat16*)pBm, out, bias, 1536, 24);
}

// round 4
// speedup vs baseline: 1.3580x; 1.3313x over previous
#include <cuda_runtime.h>
#include <cuda_bf16.h>
#include <cstdint>

// ---------------------------------------------------------------------------
// FactorizedLayer on GB300 (sm_103a) — base-PTX-target build (mma.sync path)
//   out[b,h] = 0.5*sum_l[(x.beta_hl)^2 - (x^2 . beta_hl^2)] + x.W_h + b_h
// ssq collapses via G_h[n] = sum_l beta[h,l,n]^2.
// Two bf16 mma.sync GEMMs, fp32 recovered via bf16 hi/lo K-stacking.
// R4: CTA 128x128 (8 warps, 64x32 tiles), __launch_bounds__(256,2) to force
//     regs<=128 -> 2 CTAs/SM (16 warps). Barrier bubbles of one CTA overlap
//     with the co-resident CTA's MMA phase.
// ---------------------------------------------------------------------------

#define DB 4096
#define DN 512
#define DH 1024
#define DL 8
#define RM (DH*DL)

__device__ __align__(16) __nv_bfloat16 g_Am[(size_t)DB * 1536];
__device__ __align__(16) __nv_bfloat16 g_Bm[(size_t)RM * 1536];
__device__ __align__(16) __nv_bfloat16 g_Aa[(size_t)DB * 2048];
__device__ __align__(16) __nv_bfloat16 g_Ba[(size_t)DH * 2048];

// ------------------------------- prep kernels ------------------------------

__global__ void prep_A(const float* __restrict__ x) {
    int i = blockIdx.x * 256 + threadIdx.x;          // over 4096*512
    int m = i >> 9, n = i & 511;
    float v = x[i];
    __nv_bfloat16 h = __float2bfloat16(v);
    __nv_bfloat16 l = __float2bfloat16(v - __bfloat162float(h));
    size_t bm = (size_t)m * 1536;
    g_Am[bm + n] = h; g_Am[bm + 512 + n] = h; g_Am[bm + 1024 + n] = l;
    float v2 = v * v;
    __nv_bfloat16 h2 = __float2bfloat16(v2);
    __nv_bfloat16 l2 = __float2bfloat16(v2 - __bfloat162float(h2));
    size_t ba = (size_t)m * 2048;
    g_Aa[ba + n] = h; g_Aa[ba + 512 + n] = h2;
    g_Aa[ba + 1024 + n] = h2; g_Aa[ba + 1536 + n] = l2;
}

__global__ void prep_Bm(const float* __restrict__ beta) {
    int i = blockIdx.x * 256 + threadIdx.x;          // over 8192*512
    int r = i >> 9, n = i & 511;
    float v = beta[i];
    __nv_bfloat16 h = __float2bfloat16(v);
    __nv_bfloat16 l = __float2bfloat16(v - __bfloat162float(h));
    size_t b = (size_t)r * 1536;
    g_Bm[b + n] = h; g_Bm[b + 512 + n] = l; g_Bm[b + 1024 + n] = h;
}

__global__ void prep_Ba(const float* __restrict__ beta, const float* __restrict__ W) {
    int i = blockIdx.x * 256 + threadIdx.x;          // over 1024*512
    int hh = i >> 9, n = i & 511;
    float w = W[i];
    const float* bp = beta + (size_t)hh * (DL * DN) + n;
    float g = 0.f;
#pragma unroll
    for (int l = 0; l < DL; l++) { float t = bp[l * DN]; g += t * t; }
    g *= -0.5f;
    __nv_bfloat16 wh = __float2bfloat16(w);
    __nv_bfloat16 gh = __float2bfloat16(g);
    __nv_bfloat16 gl = __float2bfloat16(g - __bfloat162float(gh));
    size_t b = (size_t)hh * 2048;
    g_Ba[b + n] = wh; g_Ba[b + 512 + n] = gh;
    g_Ba[b + 1024 + n] = gl; g_Ba[b + 1536 + n] = gh;
}

// ------------------------------- GEMM ------------------------------------

__device__ __forceinline__ uint32_t swz(uint32_t o) { return o ^ ((o >> 3) & 0x70); }

constexpr int STAGES = 3;
constexpr int TILEB = 16384;                 // bytes per operand per stage (128 rows x 128B)
constexpr int SMEMB = STAGES * TILEB * 2;    // 98304 -> 2 CTAs = 196608 <= 227KB

#define LDSM_X4(r, a)                                                           \
    asm volatile("ldmatrix.sync.aligned.m8n8.x4.shared.b16 {%0,%1,%2,%3}, [%4];"\
        : "=r"((r)[0]), "=r"((r)[1]), "=r"((r)[2]), "=r"((r)[3]) : "r"(a))

#define MMA16816(c, a, b0, b1)                                                  \
    asm volatile("mma.sync.aligned.m16n8k16.row.col.f32.bf16.bf16.f32 "         \
        "{%0,%1,%2,%3}, {%4,%5,%6,%7}, {%8,%9}, {%0,%1,%2,%3};"                 \
        : "+f"((c)[0]), "+f"((c)[1]), "+f"((c)[2]), "+f"((c)[3])                 \
        : "r"((a)[0]), "r"((a)[1]), "r"((a)[2]), "r"((a)[3]), "r"(b0), "r"(b1))

// MODE 0: aux (out = acc + bias[col]); MODE 1: main (out += 0.5*sum8(acc^2))
template <int MODE>
__global__ void __launch_bounds__(256, 2)
fm_gemm(const __nv_bfloat16* __restrict__ gA, const __nv_bfloat16* __restrict__ gB,
        float* __restrict__ out, const float* __restrict__ bias, int Kld, int KT)
{
    extern __shared__ __align__(128) char smem[];
    const uint32_t sb = (uint32_t)__cvta_generic_to_shared(smem);
    const int tid = threadIdx.x, lane = tid & 31, wid = tid >> 5;
    const int cm = blockIdx.y * 128, cn = blockIdx.x * 128;
    const int wm = (wid & 1) * 64, wn = (wid >> 1) * 32;

    // cp.async lane mapping: 32 rows x 8 chunks of 16B per pass, 4 passes
    const int lrow = tid >> 3;
    const int lchunk = tid & 7;
    const __nv_bfloat16* gArow = gA + (size_t)(cm + lrow) * Kld + lchunk * 8;
    const __nv_bfloat16* gBrow = gB + (size_t)(cn + lrow) * Kld + lchunk * 8;

    // ldmatrix lane mapping
    const int a_row = wm + (lane & 15);
    const int a_ko  = ((lane >> 4) & 1) * 16;
    const int b_mi  = lane >> 3;
    const int b_row = wn + ((b_mi >> 1) & 1) * 8 + (lane & 7);
    const int b_ko  = (b_mi & 1) * 16;

    float acc[4][4][4];
#pragma unroll
    for (int i = 0; i < 4; i++)
#pragma unroll
        for (int j = 0; j < 4; j++)
#pragma unroll
            for (int q = 0; q < 4; q++) acc[i][j][q] = 0.f;

    auto load_stage = [&](int s, int kt) {
        const uint32_t sa = sb + s * TILEB;
        const uint32_t sB = sb + STAGES * TILEB + s * TILEB;
        const int koff = kt * 64;
#pragma unroll
        for (int i = 0; i < 4; i++) {
            uint32_t da = sa + swz((lrow + i * 32) * 128 + lchunk * 16);
            const void* ga = gArow + (size_t)(i * 32) * Kld + koff;
            asm volatile("cp.async.cg.shared.global [%0], [%1], 16;" :: "r"(da), "l"(ga));
            uint32_t db = sB + swz((lrow + i * 32) * 128 + lchunk * 16);
            const void* gb = gBrow + (size_t)(i * 32) * Kld + koff;
            asm volatile("cp.async.cg.shared.global [%0], [%1], 16;" :: "r"(db), "l"(gb));
        }
    };

    auto compute = [&](int s) {
        const uint32_t sa = sb + s * TILEB;
        const uint32_t sB = sb + STAGES * TILEB + s * TILEB;
#pragma unroll
        for (int ks = 0; ks < 4; ks++) {
            uint32_t a[4][4];
#pragma unroll
            for (int mt = 0; mt < 4; mt++) {
                uint32_t addr = sa + swz((a_row + mt * 16) * 128 + ks * 32 + a_ko);
                LDSM_X4(a[mt], addr);
            }
            uint32_t b[2][4];
#pragma unroll
            for (int jj = 0; jj < 2; jj++) {
                uint32_t addr = sB + swz((b_row + jj * 16) * 128 + ks * 32 + b_ko);
                LDSM_X4(b[jj], addr);
            }
#pragma unroll
            for (int mt = 0; mt < 4; mt++)
#pragma unroll
                for (int nt = 0; nt < 4; nt++)
                    MMA16816(acc[mt][nt], a[mt], b[nt >> 1][(nt & 1) * 2], b[nt >> 1][(nt & 1) * 2 + 1]);
        }
    };

    load_stage(0, 0);
    asm volatile("cp.async.commit_group;" ::: "memory");
    load_stage(1, 1);
    asm volatile("cp.async.commit_group;" ::: "memory");

    for (int kt = 0; kt < KT; kt++) {
        asm volatile("cp.async.wait_group 1;" ::: "memory");
        __syncthreads();
        if (kt + 2 < KT) load_stage((kt + 2) % STAGES, kt + 2);
        asm volatile("cp.async.commit_group;" ::: "memory");
        compute(kt % STAGES);
    }

    // ------------------------------ epilogue ------------------------------
#pragma unroll
    for (int mt = 0; mt < 4; mt++) {
        const int row  = cm + wm + mt * 16 + (lane >> 2);
        const int row2 = row + 8;
#pragma unroll
        for (int nt = 0; nt < 4; nt++) {
            if (MODE == 0) {
                const int col = cn + wn + nt * 8 + (lane & 3) * 2;
                float2 bb = *(const float2*)(bias + col);
                float2 v0 = { acc[mt][nt][0] + bb.x, acc[mt][nt][1] + bb.y };
                float2 v1 = { acc[mt][nt][2] + bb.x, acc[mt][nt][3] + bb.y };
                *(float2*)(out + (size_t)row  * DH + col) = v0;
                *(float2*)(out + (size_t)row2 * DH + col) = v1;
            } else {
                float s0 = acc[mt][nt][0] * acc[mt][nt][0] + acc[mt][nt][1] * acc[mt][nt][1];
                float s1 = acc[mt][nt][2] * acc[mt][nt][2] + acc[mt][nt][3] * acc[mt][nt][3];
                s0 += __shfl_xor_sync(0xffffffffu, s0, 1);
                s0 += __shfl_xor_sync(0xffffffffu, s0, 2);
                s1 += __shfl_xor_sync(0xffffffffu, s1, 1);
                s1 += __shfl_xor_sync(0xffffffffu, s1, 2);
                if ((lane & 3) == 0) {
                    const int h = (cn + wn) / 8 + nt;
                    out[(size_t)row  * DH + h] += 0.5f * s0;
                    out[(size_t)row2 * DH + h] += 0.5f * s1;
                }
            }
        }
    }
}

// --------------------------------- host side --------------------------------

extern "C" void kernel_launch(void* const* d_in, const int* in_sizes, int n_in,
                              void* d_out, int out_size) {
    const float* x    = (const float*)d_in[0];
    const float* beta = (const float*)d_in[1];
    const float* W    = (const float*)d_in[2];
    const float* bias = (const float*)d_in[3];
    float* out = (float*)d_out;
    (void)in_sizes; (void)n_in; (void)out_size;

    void *pAm, *pBm, *pAa, *pBa;
    cudaGetSymbolAddress(&pAm, g_Am);
    cudaGetSymbolAddress(&pBm, g_Bm);
    cudaGetSymbolAddress(&pAa, g_Aa);
    cudaGetSymbolAddress(&pBa, g_Ba);

    cudaFuncSetAttribute((const void*)fm_gemm<0>,
                         cudaFuncAttributeMaxDynamicSharedMemorySize, SMEMB);
    cudaFuncSetAttribute((const void*)fm_gemm<1>,
                         cudaFuncAttributeMaxDynamicSharedMemorySize, SMEMB);

    prep_A <<<(DB * DN) / 256, 256>>>(x);
    prep_Bm<<<(RM * DN) / 256, 256>>>(beta);
    prep_Ba<<<(DH * DN) / 256, 256>>>(beta, W);

    // aux first: writes every out element (= linear + bias - 0.5*ssq)
    fm_gemm<0><<<dim3(DH / 128, DB / 128), 256, SMEMB>>>(
        (const __nv_bfloat16*)pAa, (const __nv_bfloat16*)pBa, out, bias, 2048, 32);
    // main: read-modify-write adds 0.5 * sum_l s^2
    fm_gemm<1><<<dim3(RM / 128, DB / 128), 256, SMEMB>>>(
        (const __nv_bfloat16*)pAm, (const __nv_bfloat16*)pBm, out, bias, 1536, 24);
}

// round 5
// speedup vs baseline: 1.3622x; 1.0031x over previous
#include <cuda_runtime.h>
#include <cuda_bf16.h>
#include <cstdint>

// ---------------------------------------------------------------------------
// FactorizedLayer on GB300 (sm_103a) — mma.sync path (base PTX target)
// R5: main GEMM restructured for operand reuse. A stored as [Xh|Xl] pairs per
// 32-k chunk (4096x1024), B as [Bh|Bl] (8192x1024). Each stage loads one pair
// tile and computes 3 products (Xh*Bh, Xh*Bl, Xl*Bh) reusing register
// fragments: 2/3 the smem traffic, 2/3 the barriers per MMA.
// Aux GEMM unchanged (bf16 4-block K=2048).
// ---------------------------------------------------------------------------

#define DB 4096
#define DN 512
#define DH 1024
#define DL 8
#define RM (DH*DL)

__device__ __align__(16) __nv_bfloat16 g_Xm[(size_t)DB * 1024];  // [Xh32|Xl32] x16
__device__ __align__(16) __nv_bfloat16 g_Bm[(size_t)RM * 1024];  // [Bh32|Bl32] x16
__device__ __align__(16) __nv_bfloat16 g_Aa[(size_t)DB * 2048];
__device__ __align__(16) __nv_bfloat16 g_Ba[(size_t)DH * 2048];

// ------------------------------- prep kernels ------------------------------

__global__ void prep_A(const float* __restrict__ x) {
    int i = blockIdx.x * 256 + threadIdx.x;          // over 4096*512
    int m = i >> 9, n = i & 511;
    float v = x[i];
    __nv_bfloat16 h = __float2bfloat16(v);
    __nv_bfloat16 l = __float2bfloat16(v - __bfloat162float(h));
    size_t bm = (size_t)m * 1024 + (size_t)(n >> 5) * 64 + (n & 31);
    g_Xm[bm] = h; g_Xm[bm + 32] = l;
    float v2 = v * v;
    __nv_bfloat16 h2 = __float2bfloat16(v2);
    __nv_bfloat16 l2 = __float2bfloat16(v2 - __bfloat162float(h2));
    size_t ba = (size_t)m * 2048;
    g_Aa[ba + n] = h; g_Aa[ba + 512 + n] = h2;
    g_Aa[ba + 1024 + n] = h2; g_Aa[ba + 1536 + n] = l2;
}

__global__ void prep_Bm(const float* __restrict__ beta) {
    int i = blockIdx.x * 256 + threadIdx.x;          // over 8192*512
    int r = i >> 9, n = i & 511;
    float v = beta[i];
    __nv_bfloat16 h = __float2bfloat16(v);
    __nv_bfloat16 l = __float2bfloat16(v - __bfloat162float(h));
    size_t b = (size_t)r * 1024 + (size_t)(n >> 5) * 64 + (n & 31);
    g_Bm[b] = h; g_Bm[b + 32] = l;
}

__global__ void prep_Ba(const float* __restrict__ beta, const float* __restrict__ W) {
    int i = blockIdx.x * 256 + threadIdx.x;          // over 1024*512
    int hh = i >> 9, n = i & 511;
    float w = W[i];
    const float* bp = beta + (size_t)hh * (DL * DN) + n;
    float g = 0.f;
#pragma unroll
    for (int l = 0; l < DL; l++) { float t = bp[l * DN]; g += t * t; }
    g *= -0.5f;
    __nv_bfloat16 wh = __float2bfloat16(w);
    __nv_bfloat16 gh = __float2bfloat16(g);
    __nv_bfloat16 gl = __float2bfloat16(g - __bfloat162float(gh));
    size_t b = (size_t)hh * 2048;
    g_Ba[b + n] = wh; g_Ba[b + 512 + n] = gh;
    g_Ba[b + 1024 + n] = gl; g_Ba[b + 1536 + n] = gh;
}

// ------------------------------- common -----------------------------------

__device__ __forceinline__ uint32_t swz(uint32_t o) { return o ^ ((o >> 3) & 0x70); }

constexpr int STAGES = 3;
constexpr int TILEB = 16384;                 // per operand per stage (128 rows x 128B)
constexpr int SMEMB = STAGES * TILEB * 2;    // 98304 -> 2 CTAs/SM

#define LDSM_X4(r, a)                                                           \
    asm volatile("ldmatrix.sync.aligned.m8n8.x4.shared.b16 {%0,%1,%2,%3}, [%4];"\
        : "=r"((r)[0]), "=r"((r)[1]), "=r"((r)[2]), "=r"((r)[3]) : "r"(a))

#define MMA16816(c, a, b0, b1)                                                  \
    asm volatile("mma.sync.aligned.m16n8k16.row.col.f32.bf16.bf16.f32 "         \
        "{%0,%1,%2,%3}, {%4,%5,%6,%7}, {%8,%9}, {%0,%1,%2,%3};"                 \
        : "+f"((c)[0]), "+f"((c)[1]), "+f"((c)[2]), "+f"((c)[3])                 \
        : "r"((a)[0]), "r"((a)[1]), "r"((a)[2]), "r"((a)[3]), "r"(b0), "r"(b1))

// ------------------------------- main GEMM ---------------------------------
// A: g_Xm (4096 x 1024), B: g_Bm (8192 x 1024); per 128B row-chunk:
// bytes [0,64) = hi half (32 k-values), [64,128) = lo half (same k-values).
// KT = 16 stages of one chunk each. 3 products per stage.

__global__ void __launch_bounds__(256, 2)
fm_main(const __nv_bfloat16* __restrict__ gA, const __nv_bfloat16* __restrict__ gB,
        float* __restrict__ out)
{
    extern __shared__ __align__(128) char smem[];
    const uint32_t sb = (uint32_t)__cvta_generic_to_shared(smem);
    const int tid = threadIdx.x, lane = tid & 31, wid = tid >> 5;
    const int cm = blockIdx.y * 128, cn = blockIdx.x * 128;
    const int wm = (wid & 1) * 64, wn = (wid >> 1) * 32;
    constexpr int Kld = 1024, KT = 16;

    const int lrow = tid >> 3;
    const int lchunk = tid & 7;
    const __nv_bfloat16* gArow = gA + (size_t)(cm + lrow) * Kld + lchunk * 8;
    const __nv_bfloat16* gBrow = gB + (size_t)(cn + lrow) * Kld + lchunk * 8;

    const int a_row = wm + (lane & 15);
    const int a_ko  = ((lane >> 4) & 1) * 16;
    const int b_mi  = lane >> 3;
    const int b_row = wn + ((b_mi >> 1) & 1) * 8 + (lane & 7);
    const int b_ko  = (b_mi & 1) * 16;

    float acc[4][4][4];
#pragma unroll
    for (int i = 0; i < 4; i++)
#pragma unroll
        for (int j = 0; j < 4; j++)
#pragma unroll
            for (int q = 0; q < 4; q++) acc[i][j][q] = 0.f;

    auto load_stage = [&](int s, int kt) {
        const uint32_t sa = sb + s * TILEB;
        const uint32_t sB = sb + STAGES * TILEB + s * TILEB;
        const int koff = kt * 64;
#pragma unroll
        for (int i = 0; i < 4; i++) {
            uint32_t da = sa + swz((lrow + i * 32) * 128 + lchunk * 16);
            const void* ga = gArow + (size_t)(i * 32) * Kld + koff;
            asm volatile("cp.async.cg.shared.global [%0], [%1], 16;" :: "r"(da), "l"(ga));
            uint32_t db = sB + swz((lrow + i * 32) * 128 + lchunk * 16);
            const void* gb = gBrow + (size_t)(i * 32) * Kld + koff;
            asm volatile("cp.async.cg.shared.global [%0], [%1], 16;" :: "r"(db), "l"(gb));
        }
    };

    auto compute = [&](int s) {
        const uint32_t sa = sb + s * TILEB;
        const uint32_t sB = sb + STAGES * TILEB + s * TILEB;
#pragma unroll
        for (int ks = 0; ks < 2; ks++) {                 // two k16 steps per chunk
            // --- load hi fragments ---
            uint32_t ah[4][4];
#pragma unroll
            for (int mt = 0; mt < 4; mt++)
                LDSM_X4(ah[mt], sa + swz((a_row + mt * 16) * 128 + ks * 32 + a_ko));
            uint32_t bh[2][4];
#pragma unroll
            for (int jj = 0; jj < 2; jj++)
                LDSM_X4(bh[jj], sB + swz((b_row + jj * 16) * 128 + ks * 32 + b_ko));
            // --- product 1: Xh * Bh ---
#pragma unroll
            for (int mt = 0; mt < 4; mt++)
#pragma unroll
                for (int nt = 0; nt < 4; nt++)
                    MMA16816(acc[mt][nt], ah[mt], bh[nt >> 1][(nt & 1) * 2], bh[nt >> 1][(nt & 1) * 2 + 1]);
            // --- product 2: Xh * Bl (reuse ah) ---
            uint32_t bl[2][4];
#pragma unroll
            for (int jj = 0; jj < 2; jj++)
                LDSM_X4(bl[jj], sB + swz((b_row + jj * 16) * 128 + 64 + ks * 32 + b_ko));
#pragma unroll
            for (int mt = 0; mt < 4; mt++)
#pragma unroll
                for (int nt = 0; nt < 4; nt++)
                    MMA16816(acc[mt][nt], ah[mt], bl[nt >> 1][(nt & 1) * 2], bl[nt >> 1][(nt & 1) * 2 + 1]);
            // --- product 3: Xl * Bh (reuse bh; load al just-in-time) ---
#pragma unroll
            for (int mt = 0; mt < 4; mt++) {
                uint32_t al[4];
                LDSM_X4(al, sa + swz((a_row + mt * 16) * 128 + 64 + ks * 32 + a_ko));
#pragma unroll
                for (int nt = 0; nt < 4; nt++)
                    MMA16816(acc[mt][nt], al, bh[nt >> 1][(nt & 1) * 2], bh[nt >> 1][(nt & 1) * 2 + 1]);
            }
        }
    };

    load_stage(0, 0);
    asm volatile("cp.async.commit_group;" ::: "memory");
    load_stage(1, 1);
    asm volatile("cp.async.commit_group;" ::: "memory");

    for (int kt = 0; kt < KT; kt++) {
        asm volatile("cp.async.wait_group 1;" ::: "memory");
        __syncthreads();
        if (kt + 2 < KT) load_stage((kt + 2) % STAGES, kt + 2);
        asm volatile("cp.async.commit_group;" ::: "memory");
        compute(kt % STAGES);
    }

    // epilogue: out[row, h] += 0.5 * sum over 8 consecutive cols of acc^2
#pragma unroll
    for (int mt = 0; mt < 4; mt++) {
        const int row  = cm + wm + mt * 16 + (lane >> 2);
        const int row2 = row + 8;
#pragma unroll
        for (int nt = 0; nt < 4; nt++) {
            float s0 = acc[mt][nt][0] * acc[mt][nt][0] + acc[mt][nt][1] * acc[mt][nt][1];
            float s1 = acc[mt][nt][2] * acc[mt][nt][2] + acc[mt][nt][3] * acc[mt][nt][3];
            s0 += __shfl_xor_sync(0xffffffffu, s0, 1);
            s0 += __shfl_xor_sync(0xffffffffu, s0, 2);
            s1 += __shfl_xor_sync(0xffffffffu, s1, 1);
            s1 += __shfl_xor_sync(0xffffffffu, s1, 2);
            if ((lane & 3) == 0) {
                const int h = (cn + wn) / 8 + nt;
                out[(size_t)row  * DH + h] += 0.5f * s0;
                out[(size_t)row2 * DH + h] += 0.5f * s1;
            }
        }
    }
}

// ------------------------------- aux GEMM ----------------------------------
// unchanged from R4 (bf16, K=2048, out = acc + bias)

__global__ void __launch_bounds__(256, 2)
fm_aux(const __nv_bfloat16* __restrict__ gA, const __nv_bfloat16* __restrict__ gB,
       float* __restrict__ out, const float* __restrict__ bias)
{
    extern __shared__ __align__(128) char smem[];
    const uint32_t sb = (uint32_t)__cvta_generic_to_shared(smem);
    const int tid = threadIdx.x, lane = tid & 31, wid = tid >> 5;
    const int cm = blockIdx.y * 128, cn = blockIdx.x * 128;
    const int wm = (wid & 1) * 64, wn = (wid >> 1) * 32;
    constexpr int Kld = 2048, KT = 32;

    const int lrow = tid >> 3;
    const int lchunk = tid & 7;
    const __nv_bfloat16* gArow = gA + (size_t)(cm + lrow) * Kld + lchunk * 8;
    const __nv_bfloat16* gBrow = gB + (size_t)(cn + lrow) * Kld + lchunk * 8;

    const int a_row = wm + (lane & 15);
    const int a_ko  = ((lane >> 4) & 1) * 16;
    const int b_mi  = lane >> 3;
    const int b_row = wn + ((b_mi >> 1) & 1) * 8 + (lane & 7);
    const int b_ko  = (b_mi & 1) * 16;

    float acc[4][4][4];
#pragma unroll
    for (int i = 0; i < 4; i++)
#pragma unroll
        for (int j = 0; j < 4; j++)
#pragma unroll
            for (int q = 0; q < 4; q++) acc[i][j][q] = 0.f;

    auto load_stage = [&](int s, int kt) {
        const uint32_t sa = sb + s * TILEB;
        const uint32_t sB = sb + STAGES * TILEB + s * TILEB;
        const int koff = kt * 64;
#pragma unroll
        for (int i = 0; i < 4; i++) {
            uint32_t da = sa + swz((lrow + i * 32) * 128 + lchunk * 16);
            const void* ga = gArow + (size_t)(i * 32) * Kld + koff;
            asm volatile("cp.async.cg.shared.global [%0], [%1], 16;" :: "r"(da), "l"(ga));
            uint32_t db = sB + swz((lrow + i * 32) * 128 + lchunk * 16);
            const void* gb = gBrow + (size_t)(i * 32) * Kld + koff;
            asm volatile("cp.async.cg.shared.global [%0], [%1], 16;" :: "r"(db), "l"(gb));
        }
    };

    auto compute = [&](int s) {
        const uint32_t sa = sb + s * TILEB;
        const uint32_t sB = sb + STAGES * TILEB + s * TILEB;
#pragma unroll
        for (int ks = 0; ks < 4; ks++) {
            uint32_t a[4][4];
#pragma unroll
            for (int mt = 0; mt < 4; mt++)
                LDSM_X4(a[mt], sa + swz((a_row + mt * 16) * 128 + ks * 32 + a_ko));
            uint32_t b[2][4];
#pragma unroll
            for (int jj = 0; jj < 2; jj++)
                LDSM_X4(b[jj], sB + swz((b_row + jj * 16) * 128 + ks * 32 + b_ko));
#pragma unroll
            for (int mt = 0; mt < 4; mt++)
#pragma unroll
                for (int nt = 0; nt < 4; nt++)
                    MMA16816(acc[mt][nt], a[mt], b[nt >> 1][(nt & 1) * 2], b[nt >> 1][(nt & 1) * 2 + 1]);
        }
    };

    load_stage(0, 0);
    asm volatile("cp.async.commit_group;" ::: "memory");
    load_stage(1, 1);
    asm volatile("cp.async.commit_group;" ::: "memory");

    for (int kt = 0; kt < KT; kt++) {
        asm volatile("cp.async.wait_group 1;" ::: "memory");
        __syncthreads();
        if (kt + 2 < KT) load_stage((kt + 2) % STAGES, kt + 2);
        asm volatile("cp.async.commit_group;" ::: "memory");
        compute(kt % STAGES);
    }

#pragma unroll
    for (int mt = 0; mt < 4; mt++) {
        const int row  = cm + wm + mt * 16 + (lane >> 2);
        const int row2 = row + 8;
#pragma unroll
        for (int nt = 0; nt < 4; nt++) {
            const int col = cn + wn + nt * 8 + (lane & 3) * 2;
            float2 bb = *(const float2*)(bias + col);
            float2 v0 = { acc[mt][nt][0] + bb.x, acc[mt][nt][1] + bb.y };
            float2 v1 = { acc[mt][nt][2] + bb.x, acc[mt][nt][3] + bb.y };
            *(float2*)(out + (size_t)row  * DH + col) = v0;
            *(float2*)(out + (size_t)row2 * DH + col) = v1;
        }
    }
}

// --------------------------------- host side --------------------------------

extern "C" void kernel_launch(void* const* d_in, const int* in_sizes, int n_in,
                              void* d_out, int out_size) {
    const float* x    = (const float*)d_in[0];
    const float* beta = (const float*)d_in[1];
    const float* W    = (const float*)d_in[2];
    const float* bias = (const float*)d_in[3];
    float* out = (float*)d_out;
    (void)in_sizes; (void)n_in; (void)out_size;

    void *pXm, *pBm, *pAa, *pBa;
    cudaGetSymbolAddress(&pXm, g_Xm);
    cudaGetSymbolAddress(&pBm, g_Bm);
    cudaGetSymbolAddress(&pAa, g_Aa);
    cudaGetSymbolAddress(&pBa, g_Ba);

    cudaFuncSetAttribute((const void*)fm_main,
                         cudaFuncAttributeMaxDynamicSharedMemorySize, SMEMB);
    cudaFuncSetAttribute((const void*)fm_aux,
                         cudaFuncAttributeMaxDynamicSharedMemorySize, SMEMB);

    prep_A <<<(DB * DN) / 256, 256>>>(x);
    prep_Bm<<<(RM * DN) / 256, 256>>>(beta);
    prep_Ba<<<(DH * DN) / 256, 256>>>(beta, W);

    // aux first: writes every out element (= linear + bias - 0.5*ssq)
    fm_aux<<<dim3(DH / 128, DB / 128), 256, SMEMB>>>(
        (const __nv_bfloat16*)pAa, (const __nv_bfloat16*)pBa, out, bias);
    // main: read-modify-write adds 0.5 * sum_l s^2
    fm_main<<<dim3(RM / 128, DB / 128), 256, SMEMB>>>(
        (const __nv_bfloat16*)pXm, (const __nv_bfloat16*)pBm, out);
}